// round 8
// baseline (speedup 1.0000x reference)
#include <cuda_runtime.h>
#include <math.h>

#define E 1024
#define H 4096
#define NCHUNK 8
#define CH_ROWS 512   // xi/h1 rows per chunk
#define CH_F4   128   // float4 per chunk (512 floats)

// Scratch (allocation-free per harness rules)
__device__ __align__(16) float g_xi[H];
__device__ __align__(16) float g_h1[H];
__device__ int g_cnt_xi[NCHUNK];
__device__ int g_cnt_h1[NCHUNK];
__device__ int g_hflag;

__device__ __forceinline__ float sigmoidf(float x) {
    return 1.0f / (1.0f + expf(-x));
}

// ---------------------------------------------------------------------------
// K0: reset chunk counters (graph replays reuse globals) + hflag = any(h0!=0)
// ---------------------------------------------------------------------------
__global__ void k_init(const float* __restrict__ h0) {
    const int t = threadIdx.x;  // 256
    if (t < NCHUNK) g_cnt_xi[t] = 0;
    if (t >= 32 && t < 32 + NCHUNK) g_cnt_h1[t - 32] = 0;
    const float4* h4 = (const float4*)h0;
    int any = 0;
    #pragma unroll
    for (int i = 0; i < 4; i++) {
        float4 v = h4[t + i * 256];
        any |= (v.x != 0.f) | (v.y != 0.f) | (v.z != 0.f) | (v.w != 0.f);
    }
    int r = __syncthreads_or(any);
    if (t == 0) g_hflag = (r != 0);
}

// ---------------------------------------------------------------------------
// Fused persistent kernel. 512 blocks x 256 threads, all co-resident
// (__launch_bounds__(256,4): 4 blocks/SM * 148 SMs = 592 slots >= 512),
// so intra-grid producer/consumer spins cannot deadlock.
//   Phase A: warp gw -> xi[gw]             (W_in, 16 MB)
//   Phase B: warp gw -> gates/h1/c1 for j=gw, consuming xi chunks (W_ih, 268MB)
//   Phase C: blocks 0..127 -> out rows, consuming h1 chunks (W_out, 16 MB)
// ---------------------------------------------------------------------------
__global__ __launch_bounds__(256, 4) void k_fused(
    const float* __restrict__ x,    const float* __restrict__ W_in,
    const float* __restrict__ b_in, const float* __restrict__ W_ih,
    const float* __restrict__ W_hh, const float* __restrict__ b_ih,
    const float* __restrict__ b_hh, const float* __restrict__ h0,
    const float* __restrict__ c0,   const float* __restrict__ W_out,
    const float* __restrict__ b_out, float* __restrict__ out)
{
    const int t = threadIdx.x;
    const int w = t >> 5, lane = t & 31;
    const int gw = blockIdx.x * 8 + w;  // 0..4095: one xi row / one gate j

    __shared__ __align__(16) float sbuf[H];  // 16 KB, reused across phases
    float4* s4 = (float4*)sbuf;

    // ---- Phase A: xi[gw] = W_in[gw,:] . x + b_in[gw]
    s4[t] = ((const float4*)x)[t];  // stage x (4 KB) in s4[0..255]
    __syncthreads();
    {
        const float4* __restrict__ wr = (const float4*)(W_in + (size_t)gw * E);
        float acc = 0.f;
        #pragma unroll
        for (int i = 0; i < 8; i++) {
            float4 a = wr[lane + 32 * i];
            float4 b = s4[lane + 32 * i];
            acc += a.x * b.x + a.y * b.y + a.z * b.z + a.w * b.w;
        }
        #pragma unroll
        for (int o = 16; o; o >>= 1) acc += __shfl_down_sync(0xFFFFFFFFu, acc, o);
        if (lane == 0) {
            g_xi[gw] = acc + b_in[gw];
            __threadfence();
            atomicAdd(&g_cnt_xi[gw >> 9], 1);
        }
    }

    // ---- Phase B: 4 gate dot-products for j = gw, chunked over xi
    const int j = gw;
    const int hflag = g_hflag;  // uniform; written by k_init before this kernel
    float a0 = 0.f, a1 = 0.f, a2 = 0.f, a3 = 0.f;
    const float4* __restrict__ w0 = (const float4*)(W_ih + (size_t)j * H);
    const float4* __restrict__ w1 = (const float4*)(W_ih + (size_t)(H + j) * H);
    const float4* __restrict__ w2 = (const float4*)(W_ih + (size_t)(2 * H + j) * H);
    const float4* __restrict__ w3 = (const float4*)(W_ih + (size_t)(3 * H + j) * H);

    for (int c = 0; c < NCHUNK; c++) {
        if (t == 0) {
            volatile int* p = g_cnt_xi + c;
            while (*p < CH_ROWS) { }
        }
        __syncthreads();  // also orders: all warps done with A's x staging
        if (t < CH_F4)
            s4[c * CH_F4 + t] = __ldcg(((const float4*)g_xi) + c * CH_F4 + t);
        __syncthreads();
        #pragma unroll
        for (int i = 0; i < 4; i++) {
            const int k = c * CH_F4 + lane + 32 * i;
            float4 xv = s4[k];
            float4 r0 = w0[k], r1 = w1[k], r2 = w2[k], r3 = w3[k];
            a0 += r0.x * xv.x + r0.y * xv.y + r0.z * xv.z + r0.w * xv.w;
            a1 += r1.x * xv.x + r1.y * xv.y + r1.z * xv.z + r1.w * xv.w;
            a2 += r2.x * xv.x + r2.y * xv.y + r2.z * xv.z + r2.w * xv.w;
            a3 += r3.x * xv.x + r3.y * xv.y + r3.z * xv.z + r3.w * xv.w;
        }
    }

    if (hflag) {  // uniform; skipped when h0 == 0 (h0 read via L2, reused)
        const float4* __restrict__ v0 = (const float4*)(W_hh + (size_t)j * H);
        const float4* __restrict__ v1 = (const float4*)(W_hh + (size_t)(H + j) * H);
        const float4* __restrict__ v2 = (const float4*)(W_hh + (size_t)(2 * H + j) * H);
        const float4* __restrict__ v3 = (const float4*)(W_hh + (size_t)(3 * H + j) * H);
        const float4* h4 = (const float4*)h0;
        #pragma unroll 4
        for (int i = 0; i < 32; i++) {
            const int k = lane + 32 * i;
            float4 hv = __ldg(h4 + k);
            float4 r0 = v0[k], r1 = v1[k], r2 = v2[k], r3 = v3[k];
            a0 += r0.x * hv.x + r0.y * hv.y + r0.z * hv.z + r0.w * hv.w;
            a1 += r1.x * hv.x + r1.y * hv.y + r1.z * hv.z + r1.w * hv.w;
            a2 += r2.x * hv.x + r2.y * hv.y + r2.z * hv.z + r2.w * hv.w;
            a3 += r3.x * hv.x + r3.y * hv.y + r3.z * hv.z + r3.w * hv.w;
        }
    }

    #pragma unroll
    for (int o = 16; o; o >>= 1) {
        a0 += __shfl_down_sync(0xFFFFFFFFu, a0, o);
        a1 += __shfl_down_sync(0xFFFFFFFFu, a1, o);
        a2 += __shfl_down_sync(0xFFFFFFFFu, a2, o);
        a3 += __shfl_down_sync(0xFFFFFFFFu, a3, o);
    }

    if (lane == 0) {
        float vi = a0 + b_ih[j]         + b_hh[j];
        float vf = a1 + b_ih[H + j]     + b_hh[H + j];
        float vg = a2 + b_ih[2 * H + j] + b_hh[2 * H + j];
        float vo = a3 + b_ih[3 * H + j] + b_hh[3 * H + j];
        float c1 = sigmoidf(vf) * c0[j] + sigmoidf(vi) * tanhf(vg);
        float h1v = sigmoidf(vo) * tanhf(c1);
        out[E + j]     = h1v;   // h1 region of output
        out[E + H + j] = c1;    // c1 region of output
        g_h1[j] = h1v;
        __threadfence();
        atomicAdd(&g_cnt_h1[j >> 9], 1);
    }

    // ---- Phase C: out[row] = W_out[row,:] . h1 + b_out[row]  (blocks 0..127)
    if (blockIdx.x < E / 8) {
        const int row = gw;  // 0..1023
        const float4* __restrict__ wr = (const float4*)(W_out + (size_t)row * H);
        float acc = 0.f;
        for (int c = 0; c < NCHUNK; c++) {
            if (t == 0) {
                volatile int* p = g_cnt_h1 + c;
                while (*p < CH_ROWS) { }
            }
            __syncthreads();  // all warps of this block are done with Phase B smem
            if (t < CH_F4)
                s4[c * CH_F4 + t] = __ldcg(((const float4*)g_h1) + c * CH_F4 + t);
            __syncthreads();
            #pragma unroll
            for (int i = 0; i < 4; i++) {
                const int k = c * CH_F4 + lane + 32 * i;
                float4 a = wr[k];
                float4 b = s4[k];
                acc += a.x * b.x + a.y * b.y + a.z * b.z + a.w * b.w;
            }
        }
        #pragma unroll
        for (int o = 16; o; o >>= 1) acc += __shfl_down_sync(0xFFFFFFFFu, acc, o);
        if (lane == 0) out[row] = acc + b_out[row];
    }
}

// ---------------------------------------------------------------------------
// Inputs (metadata order): 0:x 1:h0 2:c0 3:W_in 4:b_in 5:W_ih 6:W_hh
//                          7:b_ih 8:b_hh 9:W_out 10:b_out
// Output layout: [out (1024), h1 (4096), c1 (4096)]
// ---------------------------------------------------------------------------
extern "C" void kernel_launch(void* const* d_in, const int* in_sizes, int n_in,
                              void* d_out, int out_size) {
    const float* x     = (const float*)d_in[0];
    const float* h0    = (const float*)d_in[1];
    const float* c0    = (const float*)d_in[2];
    const float* W_in  = (const float*)d_in[3];
    const float* b_in  = (const float*)d_in[4];
    const float* W_ih  = (const float*)d_in[5];
    const float* W_hh  = (const float*)d_in[6];
    const float* b_ih  = (const float*)d_in[7];
    const float* b_hh  = (const float*)d_in[8];
    const float* W_out = (const float*)d_in[9];
    const float* b_out = (const float*)d_in[10];
    float* out = (float*)d_out;

    k_init<<<1, 256>>>(h0);
    k_fused<<<512, 256>>>(x, W_in, b_in, W_ih, W_hh, b_ih, b_hh,
                          h0, c0, W_out, b_out, out);
}